// round 2
// baseline (speedup 1.0000x reference)
#include <cuda_runtime.h>
#include <math.h>

#define NTOK 4096
#define NB   16
#define NC   256
#define NH   128
#define TOTAL (NTOK*NB)

// ---------------- device scratch (static, no allocation) ----------------
__device__ float         g_sig[TOTAL];        // sigmoid per token t = n*NB + b
__device__ unsigned char g_cat[TOTAL];        // 0 = copy x, 1 = split, 2 = discard
__device__ int           g_splitWork[TOTAL];  // per batch region b*NTOK: dst | src<<16 (dst==src)
__device__ int           g_pairWork[TOTAL];   // per batch region b*NTOK: dstDiscard | srcSplit<<16
__device__ int           g_minCnt[NB];
__device__ int           g_maskKind;          // 0 = u8/bool, 1 = f32, 2 = i32

// ---------------- mask dtype probe ----------------
// Reads only the first 65536 bytes (minimum buffer size across candidate dtypes).
// bool8: nonzero bytes at offsets %4!=0.
// f32 (1.0f = 00 00 80 3F): byte 0x3F at %4==3, zero bytes at %4!=3 except that one.
// i32 (0/1): nonzero only at %4==0.
__global__ void kProbe(const unsigned char* __restrict__ m)
{
    __shared__ int cA, c3;
    int tid = threadIdx.x;
    if (tid == 0) { cA = 0; c3 = 0; }
    __syncthreads();
    int la = 0, l3 = 0;
    for (int i = tid; i < TOTAL; i += 256) {
        unsigned char v = m[i];
        if ((i & 3) == 1 && v) la++;          // only bool8 has nonzero at %4==1
        if ((i & 3) == 3 && v == 0x3F) l3++;  // only f32(1.0) has 0x3F at %4==3
    }
    atomicAdd(&cA, la); atomicAdd(&c3, l3);
    __syncthreads();
    if (tid == 0) g_maskKind = (cA > 0) ? 0 : ((c3 > 0) ? 1 : 2);
}

// ---------------- K1: fused gate GEMM  logit -> sigmoid ----------------
// Tile: 64 tokens x 128 h-cols. 256 threads = 32 jthreads x 8 tthreads.
// Thread tile: 4 cols x 8 rows. w1 (128KB) + x rows (64KB) in smem.
__global__ __launch_bounds__(256,1) void kLogit(
    const float* __restrict__ x,  const float* __restrict__ w1,
    const float* __restrict__ b1, const float* __restrict__ w2,
    const float* __restrict__ b2)
{
    extern __shared__ float sm[];
    float* w1s = sm;            // 256*128
    float* xs  = sm + NC*NH;    // 64*256
    int tid = threadIdx.x;
    int tileBase = blockIdx.x * 64;

    { const float4* g = (const float4*)w1; float4* s = (float4*)w1s;
      for (int i = tid; i < NC*NH/4; i += 256) s[i] = g[i]; }
    { const float4* g = (const float4*)(x + (size_t)tileBase * NC); float4* s = (float4*)xs;
      for (int i = tid; i < 64*NC/4; i += 256) s[i] = g[i]; }
    __syncthreads();

    int jt = tid & 31, tt = tid >> 5;
    float acc[4][8];
    #pragma unroll
    for (int c = 0; c < 4; c++)
        #pragma unroll
        for (int r = 0; r < 8; r++) acc[c][r] = 0.f;

    const float* xb = xs + tt * 8 * NC;
    #pragma unroll 4
    for (int k = 0; k < NC; k++) {
        float4 w = *(const float4*)(w1s + k*NH + jt*4);
        #pragma unroll
        for (int r = 0; r < 8; r++) {
            float xv = xb[r*NC + k];
            acc[0][r] += w.x * xv; acc[1][r] += w.y * xv;
            acc[2][r] += w.z * xv; acc[3][r] += w.w * xv;
        }
    }

    float b1v[4], w2v[4];
    #pragma unroll
    for (int c = 0; c < 4; c++) { int j = jt*4 + c; b1v[c] = b1[j]; w2v[c] = w2[j]; }
    float bb = b2[0];

    #pragma unroll
    for (int r = 0; r < 8; r++) {
        float p = 0.f;
        #pragma unroll
        for (int c = 0; c < 4; c++) {
            float h = acc[c][r] + b1v[c];
            p += fmaxf(h, 0.f) * w2v[c];
        }
        #pragma unroll
        for (int off = 16; off > 0; off >>= 1) p += __shfl_xor_sync(0xffffffffu, p, off);
        if (jt == 0) {
            int t = tileBase + tt*8 + r;
            float logit = p + bb;
            g_sig[t] = 1.0f / (1.0f + expf(-logit));
        }
    }
}

// ---------------- block exclusive scan over 4096 packed ints (in place) ----------------
__device__ __forceinline__ void scan4096(int* A)
{
    __shared__ int wS[8];
    int tid = threadIdx.x;
    int base = tid * 16;
    int loc[16]; int sum = 0;
    #pragma unroll
    for (int i = 0; i < 16; i++) { int v = A[base + i]; loc[i] = sum; sum += v; }
    int lane = tid & 31, w = tid >> 5;
    int inc = sum;
    #pragma unroll
    for (int off = 1; off < 32; off <<= 1) {
        int t = __shfl_up_sync(0xffffffffu, inc, off);
        if (lane >= off) inc += t;
    }
    if (lane == 31) wS[w] = inc;
    __syncthreads();
    if (tid == 0) { int run = 0; for (int i = 0; i < 8; i++) { int t = wS[i]; wS[i] = run; run += t; } }
    __syncthreads();
    int off = wS[w] + (inc - sum);
    #pragma unroll
    for (int i = 0; i < 16; i++) A[base + i] = off + loc[i];
    __syncthreads();
}

// ---------------- K2: per-batch selection (1 block per batch) ----------------
__global__ __launch_bounds__(256,1) void kSelect(const void* __restrict__ maskraw)
{
    __shared__ unsigned int keys[NTOK];   // sig bits (positive floats: uint order == float order); later rank temp
    __shared__ unsigned char cat[NTOK];
    __shared__ int sIdx[NTOK];            // eq-scan temp, then split index list
    __shared__ int hist[256];
    __shared__ unsigned int sPfx;
    __shared__ int sKK, sC1, sC2;

    int b = blockIdx.x, tid = threadIdx.x;
    if (tid == 0) { sC1 = 0; sC2 = 0; }
    __syncthreads();

    int kind = g_maskKind;
    int lc1 = 0, lc2 = 0;
    for (int n = tid; n < NTOK; n += 256) {
        float s = g_sig[n*NB + b];
        bool mv;
        if (kind == 0)      mv = ((const unsigned char*)maskraw)[b*NTOK + n] != 0;
        else if (kind == 1) mv = ((const float*)maskraw)[b*NTOK + n] != 0.0f;
        else                mv = ((const int*)maskraw)[b*NTOK + n] != 0;
        unsigned char c = 0;
        if (!mv) c = (s >= 0.5f) ? 1 : 2;
        cat[n] = c; keys[n] = __float_as_uint(s);
        if (c == 1) lc1++; else if (c == 2) lc2++;
    }
    atomicAdd(&sC1, lc1); atomicAdd(&sC2, lc2);
    __syncthreads();
    int kcnt = min(sC1, sC2);   // MAX_SPLIT=10000 > 2048 max possible -> irrelevant

    if (kcnt == 0) {
        for (int n = tid; n < NTOK; n += 256) g_cat[n*NB + b] = 0;
        if (tid == 0) g_minCnt[b] = 0;
        return;
    }

    // MSB radix select, k-th largest per class; ties later broken by lowest index
    unsigned int thr[2]; int kkEq[2];
    for (int c = 1; c <= 2; c++) {
        unsigned int pfx = 0; int kk = kcnt;
        for (int p = 24; p >= 0; p -= 8) {
            hist[tid] = 0;
            __syncthreads();
            for (int n = tid; n < NTOK; n += 256) {
                if (cat[n] == (unsigned char)c) {
                    unsigned int u = keys[n];
                    if ((((unsigned long long)(u ^ pfx)) >> (p + 8)) == 0ull)
                        atomicAdd(&hist[(u >> p) & 255], 1);
                }
            }
            __syncthreads();
            if (tid == 0) {
                int cum = 0;
                for (int d = 255; d >= 0; d--) {
                    cum += hist[d];
                    if (cum >= kk) { sPfx = pfx | ((unsigned)d << p); sKK = kk - (cum - hist[d]); break; }
                }
            }
            __syncthreads();
            pfx = sPfx; kk = sKK;
            __syncthreads();
        }
        thr[c-1] = pfx; kkEq[c-1] = kk;
    }

    // eq-rank scan (stable tie-break by ascending index), packed both classes
    for (int n = tid; n < NTOK; n += 256) {
        int f = 0;
        if (cat[n] == 1 && keys[n] == thr[0]) f = 1;
        if (cat[n] == 2 && keys[n] == thr[1]) f |= 1 << 16;
        sIdx[n] = f;
    }
    __syncthreads();
    scan4096(sIdx);

    for (int n = tid; n < NTOK; n += 256) {
        unsigned char c = cat[n], c2 = 0;
        if (c == 1) {
            if (keys[n] > thr[0] || (keys[n] == thr[0] && (sIdx[n] & 0xffff) < kkEq[0])) c2 = 1;
        } else if (c == 2) {
            if (keys[n] > thr[1] || (keys[n] == thr[1] && (sIdx[n] >> 16) < kkEq[1])) c2 = 2;
        }
        cat[n] = c2;
    }
    __syncthreads();

    // rank scan for final classes (reuse keys as int temp)
    for (int n = tid; n < NTOK; n += 256)
        keys[n] = (unsigned)((cat[n] == 1 ? 1 : 0) | ((cat[n] == 2 ? 1 : 0) << 16));
    __syncthreads();
    scan4096((int*)keys);

    for (int n = tid; n < NTOK; n += 256)
        if (cat[n] == 1) sIdx[(int)(keys[n] & 0xffff)] = n;
    __syncthreads();

    for (int n = tid; n < NTOK; n += 256) {
        g_cat[n*NB + b] = cat[n];
        if (cat[n] == 1) {
            int r = (int)(keys[n] & 0xffff);
            g_splitWork[b*NTOK + r] = n | (n << 16);
        } else if (cat[n] == 2) {
            int r = (int)(keys[n] >> 16);
            g_pairWork[b*NTOK + r] = n | (sIdx[r] << 16);
        }
    }
    if (tid == 0) g_minCnt[b] = kcnt;
}

// ---------------- K3: selective z GEMM with gather/scatter ----------------
// half=0: z1 rows for split tokens. half=1: z2 rows routed to discard tokens.
// Tile: 64 work rows x 128 cols (ct picks col half). Same microkernel as K1.
__global__ __launch_bounds__(256,1) void kZ(
    const float* __restrict__ x, const float* __restrict__ ws,
    const float* __restrict__ bs, float* __restrict__ out, int half)
{
    __shared__ int witems[64];
    extern __shared__ float sm[];
    float* wss = sm;           // 256*128
    float* xs  = sm + NC*NH;   // 64*256

    int b = blockIdx.y, ct = blockIdx.z;
    int rows = g_minCnt[b];
    int r0 = blockIdx.x * 64;
    if (r0 >= rows) return;
    int tid = threadIdx.x;
    int nr = min(64, rows - r0);
    const int* work = half ? g_pairWork : g_splitWork;
    if (tid < 64) witems[tid] = (tid < nr) ? work[b*NTOK + r0 + tid] : 0;
    __syncthreads();

    { // ws tile: cols [half*256 + ct*128, +128)
        const float4* g = (const float4*)ws; float4* s = (float4*)wss;
        int cb = half*64 + ct*32;   // f4 col offset within 128-f4 row
        for (int i = tid; i < NC*NH/4; i += 256) {
            int k = i >> 5, jj = i & 31;
            s[i] = g[k*128 + cb + jj];
        }
    }
    { // gather x rows
        float4* s = (float4*)xs; const float4* g = (const float4*)x;
        for (int i = tid; i < 64*64; i += 256) {
            int r = i >> 6, q = i & 63;
            int src = witems[r] >> 16;
            s[i] = g[(src*NB + b)*64 + q];
        }
    }
    __syncthreads();

    int jt = tid & 31, tt = tid >> 5;
    float acc[4][8];
    #pragma unroll
    for (int c = 0; c < 4; c++)
        #pragma unroll
        for (int r = 0; r < 8; r++) acc[c][r] = 0.f;

    const float* xb = xs + tt * 8 * NC;
    #pragma unroll 4
    for (int k = 0; k < NC; k++) {
        float4 w = *(const float4*)(wss + k*NH + jt*4);
        #pragma unroll
        for (int r = 0; r < 8; r++) {
            float xv = xb[r*NC + k];
            acc[0][r] += w.x * xv; acc[1][r] += w.y * xv;
            acc[2][r] += w.z * xv; acc[3][r] += w.w * xv;
        }
    }

    float bsv[4];
    #pragma unroll
    for (int c = 0; c < 4; c++) bsv[c] = bs[half*NC + ct*NH + jt*4 + c];

    #pragma unroll
    for (int r = 0; r < 8; r++) {
        int gr = r0 + tt*8 + r;
        if (gr < rows) {
            int dst = witems[tt*8 + r] & 0xffff;
            float4 o;
            o.x = fmaxf(acc[0][r] + bsv[0], 0.f);
            o.y = fmaxf(acc[1][r] + bsv[1], 0.f);
            o.z = fmaxf(acc[2][r] + bsv[2], 0.f);
            o.w = fmaxf(acc[3][r] + bsv[3], 0.f);
            *(float4*)(out + (size_t)(dst*NB + b)*NC + ct*NH + jt*4) = o;
        }
    }
}

// ---------------- K4: passthrough copy for untouched rows ----------------
__global__ void kCopy(const float* __restrict__ x, float* __restrict__ out)
{
    int idx = blockIdx.x * 256 + threadIdx.x;   // float4 index, total TOTAL*64
    int t = idx >> 6;
    if (g_cat[t] == 0)
        ((float4*)out)[idx] = ((const float4*)x)[idx];
}

// ---------------- launch ----------------
extern "C" void kernel_launch(void* const* d_in, const int* in_sizes, int n_in,
                              void* d_out, int out_size)
{
    const float* x  = (const float*)d_in[0];
    const void*  mk = d_in[1];
    const float* w1 = (const float*)d_in[2];
    const float* b1 = (const float*)d_in[3];
    const float* w2 = (const float*)d_in[4];
    const float* b2 = (const float*)d_in[5];
    const float* ws = (const float*)d_in[6];
    const float* bs = (const float*)d_in[7];
    float* out = (float*)d_out;

    cudaFuncSetAttribute(kLogit, cudaFuncAttributeMaxDynamicSharedMemorySize, 196608);
    cudaFuncSetAttribute(kZ,     cudaFuncAttributeMaxDynamicSharedMemorySize, 196608);

    kProbe<<<1, 256>>>((const unsigned char*)mk);
    kLogit<<<TOTAL/64, 256, 196608>>>(x, w1, b1, w2, b2);
    kSelect<<<NB, 256>>>(mk);
    dim3 gz(32, NB, 2);
    kZ<<<gz, 256, 196608>>>(x, ws, bs, out, 0);
    kZ<<<gz, 256, 196608>>>(x, ws, bs, out, 1);
    kCopy<<<TOTAL/4, 256>>>(x, out);
}